// round 4
// baseline (speedup 1.0000x reference)
#include <cuda_runtime.h>
#include <cstdint>

// RBF kernel, D=1 degenerate:
//   out[b,i,j] = exp( -(x1[b,i] - x2[b,j])^2 / (2*scale^2) )
// B=4, N1=N2=8192 -> 1.07 GB fp32 output, DRAM-write-drain bound.
//
// R4 vs R3 (143.8us, DRAM 89.5%, L1 75.4%):
//  - 256-bit stores (st.global.cs.v8.f32, sm_100+ STG.E.256): halves STG
//    count and L1tex store wavefronts; targets the L1->LTS pacing gaps.
//  - TJ widened to 2048 (8 floats/thread), longer contiguous spans per block.
// Predicted: ~140-142us; neutral => at HW write ceiling.

static constexpr int B  = 4;
static constexpr int N1 = 8192;
static constexpr int N2 = 8192;
static constexpr int TI = 16;
static constexpr int TJ = 2048;   // 256 threads * 8 floats

__global__ __launch_bounds__(256, 6)
void rbf_kernel(const float* __restrict__ x1,
                const float* __restrict__ x2,
                const float* __restrict__ scale,
                float* __restrict__ out)
{
    const int tid = threadIdx.x;
    const int jb  = blockIdx.x;        // 0..3
    const int it  = blockIdx.y;        // 0..511
    const int b   = blockIdx.z;        // 0..3

    const int j  = jb * TJ + tid * 8;
    const int i0 = it * TI;

    // 8 x2 values for this thread (two float4 loads, 32B-aligned)
    const float4 v2a = *reinterpret_cast<const float4*>(x2 + (size_t)b * N2 + j);
    const float4 v2b = *reinterpret_cast<const float4*>(x2 + (size_t)b * N2 + j + 4);

    const float s = scale[0];
    const float c = -0.5f / (s * s);   // exp(c * d^2)

    const float* x1b = x1 + (size_t)b * N1 + i0;
    float* outb = out + ((size_t)b * N1 + i0) * (size_t)N2 + j;

    // Preload the 16 x1 values (aligned float4 loads).
    float a[TI];
#pragma unroll
    for (int q = 0; q < TI / 4; ++q) {
        const float4 t = __ldg(reinterpret_cast<const float4*>(x1b + q * 4));
        a[q * 4 + 0] = t.x;
        a[q * 4 + 1] = t.y;
        a[q * 4 + 2] = t.z;
        a[q * 4 + 3] = t.w;
    }

#pragma unroll
    for (int r = 0; r < TI; ++r) {
        const float ar = a[r];
        float d0 = ar - v2a.x;
        float d1 = ar - v2a.y;
        float d2 = ar - v2a.z;
        float d3 = ar - v2a.w;
        float d4 = ar - v2b.x;
        float d5 = ar - v2b.y;
        float d6 = ar - v2b.z;
        float d7 = ar - v2b.w;
        const float o0 = __expf(c * d0 * d0);
        const float o1 = __expf(c * d1 * d1);
        const float o2 = __expf(c * d2 * d2);
        const float o3 = __expf(c * d3 * d3);
        const float o4 = __expf(c * d4 * d4);
        const float o5 = __expf(c * d5 * d5);
        const float o6 = __expf(c * d6 * d6);
        const float o7 = __expf(c * d7 * d7);
        // 256-bit streaming store (sm_100+: STG.E.256). 32B-aligned.
        asm volatile(
            "st.global.cs.v8.f32 [%0], {%1, %2, %3, %4, %5, %6, %7, %8};"
            :: "l"(outb + (size_t)r * N2),
               "f"(o0), "f"(o1), "f"(o2), "f"(o3),
               "f"(o4), "f"(o5), "f"(o6), "f"(o7)
            : "memory");
    }
}

extern "C" void kernel_launch(void* const* d_in, const int* in_sizes, int n_in,
                              void* d_out, int out_size)
{
    const float* x1    = (const float*)d_in[0];
    const float* x2    = (const float*)d_in[1];
    const float* scale = (const float*)d_in[2];
    float* out         = (float*)d_out;

    dim3 grid(N2 / TJ, N1 / TI, B);   // (4, 512, 4)
    rbf_kernel<<<grid, 256>>>(x1, x2, scale, out);
}

// round 5
// speedup vs baseline: 1.0104x; 1.0104x over previous
#include <cuda_runtime.h>
#include <cstdint>

// RBF kernel, D=1 degenerate:
//   out[b,i,j] = exp( -(x1[b,i] - x2[b,j])^2 / (2*scale^2) )
// B=4, N1=N2=8192 -> 1.073 GB fp32 output. Pure DRAM-write-drain bound.
//
// R5 = revert to the measured optimum (R2 config):
//   TI=8, TJ=1024, 256 threads, float4 (STG.E.128) default-cache stores.
// Evidence: R2=143.84us (DRAM 89.8%), R3 (TI=16 + .cs)=143.87, R4 (v8
// stores)=146.6. All configs pin DRAM ~90% / ~7.1 TB/s with zero DRAM read
// traffic -> the residual ~10% is HBM write-turnaround/refresh, i.e. the
// hardware ceiling for a write-only stream. Keep only the x1 float4 preload
// (verified neutral, fewer LDGs).

static constexpr int B  = 4;
static constexpr int N1 = 8192;
static constexpr int N2 = 8192;
static constexpr int TI = 8;
static constexpr int TJ = 1024;   // 256 threads * float4

__global__ __launch_bounds__(256, 8)
void rbf_kernel(const float* __restrict__ x1,
                const float* __restrict__ x2,
                const float* __restrict__ scale,
                float* __restrict__ out)
{
    const int tid = threadIdx.x;
    const int jb  = blockIdx.x;        // 0..7   (fast-varying -> concurrent
    const int it  = blockIdx.y;        // 0..1023  blocks write one contiguous
    const int b   = blockIdx.z;        // 0..3     256KB region together)

    const int j  = jb * TJ + tid * 4;
    const int i0 = it * TI;

    // x2 chunk for this thread (registers); x2 is L2-resident (32KB/batch).
    const float4 v2 = *reinterpret_cast<const float4*>(x2 + (size_t)b * N2 + j);

    const float s = scale[0];
    const float c = -0.5f / (s * s);   // out = exp(c * d^2)

    const float* x1b = x1 + (size_t)b * N1 + i0;
    float* outb = out + ((size_t)b * N1 + i0) * (size_t)N2 + j;

    // Preload the 8 x1 values as 2x float4 (i0 % 8 == 0, aligned).
    float a[TI];
#pragma unroll
    for (int q = 0; q < TI / 4; ++q) {
        const float4 t = __ldg(reinterpret_cast<const float4*>(x1b + q * 4));
        a[q * 4 + 0] = t.x;
        a[q * 4 + 1] = t.y;
        a[q * 4 + 2] = t.z;
        a[q * 4 + 3] = t.w;
    }

#pragma unroll
    for (int r = 0; r < TI; ++r) {
        const float ar = a[r];
        const float dx0 = ar - v2.x;
        const float dx1 = ar - v2.y;
        const float dx2 = ar - v2.z;
        const float dx3 = ar - v2.w;
        float4 o;
        o.x = __expf(c * dx0 * dx0);
        o.y = __expf(c * dx1 * dx1);
        o.z = __expf(c * dx2 * dx2);
        o.w = __expf(c * dx3 * dx3);
        *reinterpret_cast<float4*>(outb + (size_t)r * N2) = o;
    }
}

extern "C" void kernel_launch(void* const* d_in, const int* in_sizes, int n_in,
                              void* d_out, int out_size)
{
    const float* x1    = (const float*)d_in[0];
    const float* x2    = (const float*)d_in[1];
    const float* scale = (const float*)d_in[2];
    float* out         = (float*)d_out;

    dim3 grid(N2 / TJ, N1 / TI, B);   // (8, 1024, 4)
    rbf_kernel<<<grid, 256>>>(x1, x2, scale, out);
}

// round 6
// speedup vs baseline: 1.0128x; 1.0024x over previous
#include <cuda_runtime.h>
#include <cstdint>

// RBF kernel, D=1 degenerate case:
//   out[b,i,j] = exp( -(x1[b,i] - x2[b,j])^2 / (2*scale^2) )
// B=4, N1=N2=8192. Output = 1.073 GB fp32 -> pure DRAM-write-drain bound.
//
// FINAL (R2 config, best measured: 143.84us harness / 142.66us ncu):
//   TI=8 x TJ=1024 tile, 256 threads, one float4 of x2 in registers/thread,
//   scalar x1 broadcast loads (L1-hot), coalesced STG.E.128 default-cache.
// Ceiling evidence: 4 store-scheme/tiling variants all pin
// dram__cycles_active at 89-90% (~7.1 TB/s) with zero DRAM reads; no other
// pipe within 2x of binding. Residual ~10% = HBM write-turnaround/refresh.

static constexpr int B  = 4;
static constexpr int N1 = 8192;
static constexpr int N2 = 8192;
static constexpr int TI = 8;
static constexpr int TJ = 1024;   // 256 threads * float4

__global__ __launch_bounds__(256, 8)
void rbf_kernel(const float* __restrict__ x1,
                const float* __restrict__ x2,
                const float* __restrict__ scale,
                float* __restrict__ out)
{
    const int tid = threadIdx.x;
    const int jb  = blockIdx.x;        // 0..N2/TJ-1  (8)
    const int it  = blockIdx.y;        // 0..N1/TI-1  (1024)
    const int b   = blockIdx.z;        // 0..B-1

    const int j  = jb * TJ + tid * 4;
    const int i0 = it * TI;

    // x2 chunk for this thread (registers); x2 is L2-resident (32KB/batch).
    const float4 v2 = *reinterpret_cast<const float4*>(x2 + (size_t)b * N2 + j);

    const float s = scale[0];
    const float c = -0.5f / (s * s);   // out = exp(c * d^2)

    const float* x1b = x1 + (size_t)b * N1 + i0;
    float* outb = out + ((size_t)b * N1 + i0) * (size_t)N2 + j;

#pragma unroll
    for (int r = 0; r < TI; ++r) {
        const float a = __ldg(x1b + r);   // uniform across block, L1-hot
        const float dx0 = a - v2.x;
        const float dx1 = a - v2.y;
        const float dx2 = a - v2.z;
        const float dx3 = a - v2.w;
        float4 o;
        o.x = __expf(c * dx0 * dx0);
        o.y = __expf(c * dx1 * dx1);
        o.z = __expf(c * dx2 * dx2);
        o.w = __expf(c * dx3 * dx3);
        *reinterpret_cast<float4*>(outb + (size_t)r * N2) = o;
    }
}

extern "C" void kernel_launch(void* const* d_in, const int* in_sizes, int n_in,
                              void* d_out, int out_size)
{
    const float* x1    = (const float*)d_in[0];
    const float* x2    = (const float*)d_in[1];
    const float* scale = (const float*)d_in[2];
    float* out         = (float*)d_out;

    dim3 grid(N2 / TJ, N1 / TI, B);   // (8, 1024, 4)
    rbf_kernel<<<grid, 256>>>(x1, x2, scale, out);
}